// round 12
// baseline (speedup 1.0000x reference)
#include <cuda_runtime.h>
#include <stdint.h>

// ---------------------------------------------------------------------------
// Sparse average pooling via L2-resident presence-bitmap ranks.
//
// Effective reference key (JAX x64 disabled -> int32 wrap drops batch term):
//   q0*2^22 + q1*2^11 + q2, q_i = coord_i>>1 < 512.  27-bit keyspace.
// rank = # distinct smaller keys = jnp.unique inverse (sort-equivalent,
// verified). Ranks DENSE in [0,nvox): empty slots = contiguous tail.
//
// This round: INTERLEAVED segments — 32B = [prefix(4B) | 224 bitmap bits].
// One random L2 sector per point yields both prefix and popcount data.
// k_rank: 2 points/thread (uint2 keys) for doubled MLP.
// ---------------------------------------------------------------------------

#define KEYSPACE  (1u << 27)
#define SEG_BITS  224u
#define NSEG      ((KEYSPACE + SEG_BITS - 1u) / SEG_BITS)   // 599187
#define NBLK_SCAN ((NSEG + 255u) / 256u)                    // 2341
#define NSEG_A    (NBLK_SCAN * 256u)                        // 599296 (padded)
#define MAXN      (1 << 21)

__device__ uint32_t g_seg[NSEG_A * 8u];   // [pref, w0..w6] per segment, 32B each
__device__ uint32_t g_state[NBLK_SCAN + 3u];  // lookback state (val<<2 | flag)
__device__ uint32_t g_keys[MAXN];
__device__ uint32_t g_counts[MAXN];
__device__ uint32_t g_ranks[MAXN];
__device__ uint32_t g_multi[MAXN];
__device__ uint32_t g_nmulti;
__device__ uint32_t g_nvox;

__device__ __forceinline__ uint32_t make_key(int4 c) {
    uint32_t q0 = ((uint32_t)c.x) >> 1;
    uint32_t q1 = ((uint32_t)c.y) >> 1;
    uint32_t q2 = ((uint32_t)c.z) >> 1;
    return (q0 << 18) | (q1 << 9) | q2;   // batch excluded (int32 wrap in ref)
}

__device__ __forceinline__ uint32_t popc4(uint4 v) {
    return __popc(v.x) + __popc(v.y) + __popc(v.z) + __popc(v.w);
}

// A: zero segment array + counts + scan state + worklist counter
__global__ void k_zero(int n) {
    uint32_t tid = blockIdx.x * blockDim.x + threadIdx.x;
    uint32_t stride = gridDim.x * blockDim.x;
    uint4 z = make_uint4(0u, 0u, 0u, 0u);
    uint4* sg = reinterpret_cast<uint4*>(g_seg);
    for (uint32_t i = tid; i < NSEG_A * 2u; i += stride) sg[i] = z;
    for (uint32_t i = tid; i < (uint32_t)n; i += stride) g_counts[i] = 0u;
    for (uint32_t i = tid; i < NBLK_SCAN; i += stride) g_state[i] = 0u;
    if (tid == 0) g_nmulti = 0u;
}

// B: set presence bits (interleaved layout) + stash keys
__global__ void k_setbits(const int4* __restrict__ coords, int n) {
    int i = blockIdx.x * blockDim.x + threadIdx.x;
    if (i >= n) return;
    uint32_t key = make_key(coords[i]);
    g_keys[i] = key;
    uint32_t seg   = key / SEG_BITS;
    uint32_t inner = key - seg * SEG_BITS;
    atomicOr(&g_seg[seg * 8u + 1u + (inner >> 5)], 1u << (inner & 31u));
}

// C: popcount + decoupled-lookback scan; writes ABSOLUTE exclusive prefix
//    into slot 0 of each 32B segment. One thread per segment.
__global__ void __launch_bounds__(256) k_scan() {
    __shared__ uint32_t sh[256];
    __shared__ uint32_t sh_excl;
    uint32_t b = blockIdx.x, t = threadIdx.x;
    uint32_t s = b * 256u + t;
    const uint4* p = reinterpret_cast<const uint4*>(g_seg) + 2u * s;
    uint4 a = p[0], d = p[1];
    uint32_t tsum = __popc(a.y) + __popc(a.z) + __popc(a.w) + popc4(d);
    sh[t] = tsum;
    __syncthreads();
    for (int off = 1; off < 256; off <<= 1) {
        uint32_t v = 0;
        if ((int)t >= off) v = sh[t - off];
        __syncthreads();
        if ((int)t >= off) sh[t] += v;
        __syncthreads();
    }
    uint32_t texcl = sh[t] - tsum;

    if (t == 0) {
        uint32_t total = sh[255];
        uint32_t excl;
        if (b == 0) {
            atomicExch(&g_state[0], (total << 2) | 2u);
            excl = 0u;
        } else {
            atomicExch(&g_state[b], (total << 2) | 1u);   // aggregate ready
            uint32_t sum = 0; int i = (int)b - 1;
            while (true) {
                uint32_t v = atomicOr(&g_state[i], 0u);
                uint32_t f = v & 3u;
                if (f == 0u) { __nanosleep(20); continue; }
                sum += v >> 2;
                if (f == 2u) break;
                --i;
            }
            atomicExch(&g_state[b], ((sum + total) << 2) | 2u);  // inclusive
            excl = sum;
        }
        sh_excl = excl;
        if (b == NBLK_SCAN - 1u) g_nvox = excl + total;
    }
    __syncthreads();
    g_seg[s * 8u] = sh_excl + texcl;   // prefix into slot 0
}

// rank of one point from its key: ONE 32B sector (prefix + 7 bitmap words)
__device__ __forceinline__ uint32_t rank_of(uint32_t key) {
    uint32_t seg   = key / SEG_BITS;
    uint32_t inner = key - seg * SEG_BITS;
    const uint4* p = reinterpret_cast<const uint4*>(g_seg) + 2u * seg;
    uint4 a = p[0], d = p[1];
    uint32_t widx = inner >> 5;        // 0..6
    uint32_t mask = (1u << (inner & 31u)) - 1u;
    uint32_t words[7] = {a.y, a.z, a.w, d.x, d.y, d.z, d.w};
    uint32_t r = a.x;                  // segment's absolute exclusive prefix
#pragma unroll
    for (uint32_t idx = 0; idx < 7; idx++) {
        if (idx < widx)       r += __popc(words[idx]);
        else if (idx == widx) r += __popc(words[idx] & mask);
    }
    return r;
}

// D: per-point rank, 2 adjacent points per thread (uint2 key load) + counts
//    + multi-voxel worklist
__global__ void k_rank(int n) {
    uint32_t t = blockIdx.x * blockDim.x + threadIdx.x;
    uint32_t i0 = t * 2u;
    if (i0 >= (uint32_t)n) return;
    bool two = (i0 + 1u) < (uint32_t)n;
    uint2 kk = reinterpret_cast<const uint2*>(g_keys)[t];
    uint32_t r0 = rank_of(kk.x);
    uint32_t r1 = two ? rank_of(kk.y) : 0u;
    if (two) {
        reinterpret_cast<uint2*>(g_ranks)[t] = make_uint2(r0, r1);
    } else {
        g_ranks[i0] = r0;
    }
    uint32_t old0 = atomicAdd(&g_counts[r0], 1u);
    if (old0 == 1u) { uint32_t s = atomicAdd(&g_nmulti, 1u); g_multi[s] = r0; }
    if (two) {
        uint32_t old1 = atomicAdd(&g_counts[r1], 1u);
        if (old1 == 1u) { uint32_t s = atomicAdd(&g_nmulti, 1u); g_multi[s] = r1; }
    }
}

// E: unconditional direct store; 8-lane group per point, 2x float4 (MLP=2).
//    Races on multi slots are benign: k_prep re-zeros them afterwards.
__global__ void k_direct(const int* __restrict__ coords, const float* __restrict__ feats,
                         float* __restrict__ outc, float* __restrict__ outf, int n) {
    uint32_t gw   = (blockIdx.x * blockDim.x + threadIdx.x) >> 5;
    uint32_t lane = threadIdx.x & 31u;
    uint32_t q    = lane >> 3;            // 0..3: point within warp
    uint32_t ql   = lane & 7u;
    uint32_t pt   = gw * 4u + q;
    if (pt >= (uint32_t)n) return;
    uint32_t r = g_ranks[pt];
    const float4* fin = reinterpret_cast<const float4*>(feats + 64ull * pt);
    float4 v0 = __ldcs(fin + ql);
    float4 v1 = __ldcs(fin + ql + 8);
    float4* fo = reinterpret_cast<float4*>(outf + 64ull * r);
    __stcs(fo + ql, v0);
    __stcs(fo + ql + 8, v1);
    if (ql == 0) {
        int4 c = reinterpret_cast<const int4*>(coords)[pt];
        float4 cf = make_float4((float)c.x, (float)c.y, (float)c.z, (float)c.w);
        __stcs(reinterpret_cast<float4*>(outc + 4ull * r), cf);
    }
}

// F: zero the contiguous empty tail [nvox, n) + the multi-slot worklist.
__global__ void k_prep(float* __restrict__ outc, float* __restrict__ outf, int n) {
    uint32_t gw   = (blockIdx.x * blockDim.x + threadIdx.x) >> 5;
    uint32_t lane = threadIdx.x & 31u;
    uint32_t nw   = (gridDim.x * blockDim.x) >> 5;
    uint32_t nv   = g_nvox;
    uint32_t nm   = g_nmulti;
    uint32_t tail = (uint32_t)n - nv;
    uint32_t tot  = tail + nm;
    float4 z = make_float4(0.f, 0.f, 0.f, 0.f);
    for (uint32_t i = gw; i < tot; i += nw) {
        uint32_t s = (i < tail) ? (nv + i) : g_multi[i - tail];
        if (lane < 16u)       reinterpret_cast<float4*>(outf + 64ull * s)[lane] = z;
        else if (lane == 16u) reinterpret_cast<float4*>(outc + 4ull * s)[0] = z;
    }
}

// G: atomic accumulate for multi-voxel points only (warp ballot + cooperative)
__global__ void k_multi(const int* __restrict__ coords, const float* __restrict__ feats,
                        float* __restrict__ outc, float* __restrict__ outf, int n) {
    uint32_t gw   = (blockIdx.x * blockDim.x + threadIdx.x) >> 5;
    uint32_t lane = threadIdx.x & 31u;
    uint32_t pt   = gw * 32u + lane;
    bool valid = pt < (uint32_t)n;
    uint32_t r = valid ? g_ranks[pt] : 0u;
    uint32_t c = valid ? g_counts[r] : 0u;
    uint32_t m = __ballot_sync(0xffffffffu, valid && c > 1u);
    while (m) {
        uint32_t j = __ffs(m) - 1u;
        m &= m - 1u;
        uint32_t rj  = __shfl_sync(0xffffffffu, r, j);
        uint32_t ptj = gw * 32u + j;
        float2 v = reinterpret_cast<const float2*>(feats + 64ull * ptj)[lane];
        float* fs = outf + 64ull * rj + 2ull * lane;
        atomicAdd(fs, v.x);
        atomicAdd(fs + 1, v.y);
        if (lane < 4u)
            atomicAdd(&outc[4ull * rj + lane], (float)coords[4ull * ptj + lane]);
    }
}

// H: finalize multi voxels from worklist (warp per voxel)
__global__ void k_final(float* __restrict__ outc, float* __restrict__ outf) {
    uint32_t gw   = (blockIdx.x * blockDim.x + threadIdx.x) >> 5;
    uint32_t lane = threadIdx.x & 31u;
    uint32_t nw   = (gridDim.x * blockDim.x) >> 5;
    uint32_t nm   = g_nmulti;
    for (uint32_t v = gw; v < nm; v += nw) {
        uint32_t r = g_multi[v];
        float fc = (float)g_counts[r];
        float* f = outf + 64ull * r + 2ull * lane;
        f[0] = f[0] / fc;
        f[1] = f[1] / fc;
        if (lane < 4u) {
            float* cc = outc + 4ull * r + lane;
            cc[0] = rintf(cc[0] / fc);   // half-to-even == jnp.round (exact sums)
        }
    }
}

extern "C" void kernel_launch(void* const* d_in, const int* in_sizes, int n_in,
                              void* d_out, int out_size) {
    // coords is the smaller input (4 ints/point) vs feats (64 floats/point)
    const int*   coords;
    const float* feats;
    int n;
    if (in_sizes[0] <= in_sizes[1]) {
        coords = (const int*)d_in[0];
        feats  = (const float*)d_in[1];
        n = in_sizes[0] / 4;
    } else {
        coords = (const int*)d_in[1];
        feats  = (const float*)d_in[0];
        n = in_sizes[1] / 4;
    }
    if (n <= 0 || n > MAXN) return;

    float* outc = (float*)d_out;             // [n,4]  pooled coords (as f32)
    float* outf = outc + 4ull * (size_t)n;   // [n,64] pooled feats

    const int4* c4 = reinterpret_cast<const int4*>(coords);
    int nb = (n + 255) / 256;

    k_zero<<<2048, 256>>>(n);
    k_setbits<<<nb, 256>>>(c4, n);
    k_scan<<<(int)NBLK_SCAN, 256>>>();
    {
        int threads2 = (n + 1) / 2;
        k_rank<<<(threads2 + 255) / 256, 256>>>(n);
    }
    {
        long long warps = (n + 3) / 4;
        int blocks = (int)((warps * 32 + 255) / 256);
        k_direct<<<blocks, 256>>>(coords, feats, outc, outf, n);
    }
    k_prep<<<256, 256>>>(outc, outf, n);
    k_multi<<<nb, 256>>>(coords, feats, outc, outf, n);
    k_final<<<256, 256>>>(outc, outf);
}

// round 13
// speedup vs baseline: 1.1883x; 1.1883x over previous
#include <cuda_runtime.h>
#include <stdint.h>

// ---------------------------------------------------------------------------
// Sparse average pooling via L2-resident presence-bitmap ranks.
//
// Effective reference key (JAX x64 disabled -> int32 wrap drops batch term):
//   q0*2^22 + q1*2^11 + q2, q_i = coord_i>>1 < 512.  27-bit keyspace.
// key = (q0<<18)|(q1<<9)|q2 (order-isomorphic). Bitmap 16MB, L2-resident.
// rank = # distinct smaller keys = jnp.unique inverse (sort-equivalent,
// verified). Ranks DENSE in [0,nvox): empty slots = contiguous tail.
//
// This round: OUTPUT GATHER. k_rank also builds the inverse map
// g_inv[rank]=point (exact for singleton slots). The output kernel walks
// slots sequentially: singleton -> gather feats[pt], else -> zeros.
// All output writes are fully sequential streaming stores.
// ---------------------------------------------------------------------------

#define NBM_WORDS (1u << 22)    // 2^27 bits / 32 = 16 MB
#define SEGW      4u            // 4 words = 128 bits per segment
#define NSEG      (NBM_WORDS / SEGW)        // 1,048,576 segments (4MB prefix)
#define CHUNK_SEGS 1024u
#define NCHUNKB   (NSEG / CHUNK_SEGS)       // 1024 scan chunks
#define MAXN      (1 << 21)

__device__ uint32_t g_bitmap[NBM_WORDS];
__device__ uint32_t g_segpref[NSEG];   // ABSOLUTE exclusive prefix per segment
__device__ uint32_t g_state[NCHUNKB];  // decoupled-lookback state (val<<2 | flag)
__device__ uint32_t g_keys[MAXN];      // precomputed per-point keys
__device__ uint32_t g_counts[MAXN];
__device__ uint32_t g_ranks[MAXN];
__device__ uint32_t g_inv[MAXN];       // inverse: slot -> point (singletons exact)
__device__ uint32_t g_multi[MAXN];     // worklist of multi-point voxel slots
__device__ uint32_t g_nmulti;
__device__ uint32_t g_nvox;

__device__ __forceinline__ uint32_t make_key(int4 c) {
    uint32_t q0 = ((uint32_t)c.x) >> 1;
    uint32_t q1 = ((uint32_t)c.y) >> 1;
    uint32_t q2 = ((uint32_t)c.z) >> 1;
    return (q0 << 18) | (q1 << 9) | q2;   // batch excluded (int32 wrap in ref)
}

__device__ __forceinline__ uint32_t popc4(uint4 v) {
    return __popc(v.x) + __popc(v.y) + __popc(v.z) + __popc(v.w);
}

// A: zero bitmap + counts + scan state + worklist counter
__global__ void k_zero(int n) {
    uint32_t tid = blockIdx.x * blockDim.x + threadIdx.x;
    uint32_t stride = gridDim.x * blockDim.x;
    uint4 z = make_uint4(0u, 0u, 0u, 0u);
    uint4* bm = reinterpret_cast<uint4*>(g_bitmap);
    for (uint32_t i = tid; i < NBM_WORDS / 4; i += stride) bm[i] = z;
    for (uint32_t i = tid; i < (uint32_t)n; i += stride) g_counts[i] = 0u;
    for (uint32_t i = tid; i < NCHUNKB; i += stride) g_state[i] = 0u;
    if (tid == 0) g_nmulti = 0u;
}

// B: set presence bits + stash keys
__global__ void k_setbits(const int4* __restrict__ coords, int n) {
    int i = blockIdx.x * blockDim.x + threadIdx.x;
    if (i >= n) return;
    uint32_t key = make_key(coords[i]);
    g_keys[i] = key;
    atomicOr(&g_bitmap[key >> 5], 1u << (key & 31u));
}

// C: fused popcount + scan, decoupled lookback. Block b handles 1024 segments;
//    writes ABSOLUTE exclusive prefix per segment.
__global__ void __launch_bounds__(256) k_scan() {
    __shared__ uint32_t sh[256];
    __shared__ uint32_t sh_excl;
    uint32_t b = blockIdx.x, t = threadIdx.x;
    uint32_t segBase = b * CHUNK_SEGS + t * 4u;   // 4 segments per thread
    const uint4* p = reinterpret_cast<const uint4*>(&g_bitmap[segBase * SEGW]);
    uint4 w0 = p[0], w1 = p[1], w2 = p[2], w3 = p[3];
    uint32_t s0 = popc4(w0);
    uint32_t s1 = popc4(w1);
    uint32_t s2 = popc4(w2);
    uint32_t s3 = popc4(w3);
    uint32_t tsum = s0 + s1 + s2 + s3;
    sh[t] = tsum;
    __syncthreads();
    for (int off = 1; off < 256; off <<= 1) {
        uint32_t v = 0;
        if ((int)t >= off) v = sh[t - off];
        __syncthreads();
        if ((int)t >= off) sh[t] += v;
        __syncthreads();
    }
    uint32_t texcl = sh[t] - tsum;

    if (t == 0) {
        uint32_t total = sh[255];
        uint32_t excl;
        if (b == 0) {
            atomicExch(&g_state[0], (total << 2) | 2u);
            excl = 0u;
        } else {
            atomicExch(&g_state[b], (total << 2) | 1u);   // aggregate ready
            uint32_t sum = 0; int i = (int)b - 1;
            while (true) {
                uint32_t v = atomicOr(&g_state[i], 0u);
                uint32_t f = v & 3u;
                if (f == 0u) { __nanosleep(20); continue; }
                sum += v >> 2;
                if (f == 2u) break;
                --i;
            }
            atomicExch(&g_state[b], ((sum + total) << 2) | 2u);  // inclusive
            excl = sum;
        }
        sh_excl = excl;
        if (b == NCHUNKB - 1) g_nvox = excl + total;
    }
    __syncthreads();
    uint32_t base = sh_excl + texcl;
    g_segpref[segBase]     = base;
    g_segpref[segBase + 1] = base + s0;
    g_segpref[segBase + 2] = base + s0 + s1;
    g_segpref[segBase + 3] = base + s0 + s1 + s2;
}

// D: per-point rank + counts + inverse map + multi-voxel worklist
__global__ void k_rank(int n) {
    int i = blockIdx.x * blockDim.x + threadIdx.x;
    if (i >= n) return;
    uint32_t key  = g_keys[i];
    uint32_t bit  = key & 31u;
    uint32_t w    = key >> 5;
    uint32_t seg  = w >> 2;          // 4 words per segment
    uint32_t widx = w & 3u;
    uint32_t r = g_segpref[seg];
    uint32_t mask = (1u << bit) - 1u;
    uint4 v = reinterpret_cast<const uint4*>(g_bitmap)[seg];
    uint32_t words[4] = {v.x, v.y, v.z, v.w};
#pragma unroll
    for (uint32_t idx = 0; idx < 4; idx++) {
        if (idx < widx)       r += __popc(words[idx]);
        else if (idx == widx) r += __popc(words[idx] & mask);
    }
    g_ranks[i] = r;
    g_inv[r] = (uint32_t)i;          // exact for singleton slots; racy (unused) else
    uint32_t old = atomicAdd(&g_counts[r], 1u);
    if (old == 1u) {                 // second arrival -> multi voxel
        uint32_t s = atomicAdd(&g_nmulti, 1u);
        g_multi[s] = r;
    }
}

// E: sequential output writer. 8-lane group per slot (4 slots/warp).
//    count==1 -> gather point's feats/coords; else -> zeros (covers empty
//    tail AND pre-zeroes multi slots for k_multi). Writes fully sequential.
__global__ void k_gather(const int* __restrict__ coords, const float* __restrict__ feats,
                         float* __restrict__ outc, float* __restrict__ outf, int n) {
    uint32_t gw   = (blockIdx.x * blockDim.x + threadIdx.x) >> 5;
    uint32_t lane = threadIdx.x & 31u;
    uint32_t q    = lane >> 3;            // 0..3: slot within warp
    uint32_t ql   = lane & 7u;
    uint32_t s    = gw * 4u + q;
    if (s >= (uint32_t)n) return;
    uint32_t c = g_counts[s];
    float4 v0 = make_float4(0.f, 0.f, 0.f, 0.f);
    float4 v1 = v0;
    float4 cf = v0;
    if (c == 1u) {
        uint32_t pt = g_inv[s];
        const float4* fin = reinterpret_cast<const float4*>(feats + 64ull * pt);
        v0 = __ldcs(fin + ql);
        v1 = __ldcs(fin + ql + 8);
        if (ql == 0u) {
            int4 cc = reinterpret_cast<const int4*>(coords)[pt];
            cf = make_float4((float)cc.x, (float)cc.y, (float)cc.z, (float)cc.w);
        }
    }
    float4* fo = reinterpret_cast<float4*>(outf + 64ull * s);
    __stcs(fo + ql, v0);
    __stcs(fo + ql + 8, v1);
    if (ql == 0u)
        __stcs(reinterpret_cast<float4*>(outc + 4ull * s), cf);
}

// F: atomic accumulate for multi-voxel points only (warp ballot + cooperative)
__global__ void k_multi(const int* __restrict__ coords, const float* __restrict__ feats,
                        float* __restrict__ outc, float* __restrict__ outf, int n) {
    uint32_t gw   = (blockIdx.x * blockDim.x + threadIdx.x) >> 5;
    uint32_t lane = threadIdx.x & 31u;
    uint32_t pt   = gw * 32u + lane;
    bool valid = pt < (uint32_t)n;
    uint32_t r = valid ? g_ranks[pt] : 0u;
    uint32_t c = valid ? g_counts[r] : 0u;
    uint32_t m = __ballot_sync(0xffffffffu, valid && c > 1u);
    while (m) {
        uint32_t j = __ffs(m) - 1u;
        m &= m - 1u;
        uint32_t rj  = __shfl_sync(0xffffffffu, r, j);
        uint32_t ptj = gw * 32u + j;
        float2 v = reinterpret_cast<const float2*>(feats + 64ull * ptj)[lane];
        float* fs = outf + 64ull * rj + 2ull * lane;
        atomicAdd(fs, v.x);
        atomicAdd(fs + 1, v.y);
        if (lane < 4u)
            atomicAdd(&outc[4ull * rj + lane], (float)coords[4ull * ptj + lane]);
    }
}

// G: finalize multi voxels from worklist (warp per voxel)
__global__ void k_final(float* __restrict__ outc, float* __restrict__ outf) {
    uint32_t gw   = (blockIdx.x * blockDim.x + threadIdx.x) >> 5;
    uint32_t lane = threadIdx.x & 31u;
    uint32_t nw   = (gridDim.x * blockDim.x) >> 5;
    uint32_t nm   = g_nmulti;
    for (uint32_t v = gw; v < nm; v += nw) {
        uint32_t r = g_multi[v];
        float fc = (float)g_counts[r];
        float* f = outf + 64ull * r + 2ull * lane;
        f[0] = f[0] / fc;
        f[1] = f[1] / fc;
        if (lane < 4u) {
            float* cc = outc + 4ull * r + lane;
            cc[0] = rintf(cc[0] / fc);   // half-to-even == jnp.round (exact sums)
        }
    }
}

extern "C" void kernel_launch(void* const* d_in, const int* in_sizes, int n_in,
                              void* d_out, int out_size) {
    // coords is the smaller input (4 ints/point) vs feats (64 floats/point)
    const int*   coords;
    const float* feats;
    int n;
    if (in_sizes[0] <= in_sizes[1]) {
        coords = (const int*)d_in[0];
        feats  = (const float*)d_in[1];
        n = in_sizes[0] / 4;
    } else {
        coords = (const int*)d_in[1];
        feats  = (const float*)d_in[0];
        n = in_sizes[1] / 4;
    }
    if (n <= 0 || n > MAXN) return;

    float* outc = (float*)d_out;             // [n,4]  pooled coords (as f32)
    float* outf = outc + 4ull * (size_t)n;   // [n,64] pooled feats

    const int4* c4 = reinterpret_cast<const int4*>(coords);
    int nb = (n + 255) / 256;

    k_zero<<<2048, 256>>>(n);
    k_setbits<<<nb, 256>>>(c4, n);
    k_scan<<<NCHUNKB, 256>>>();
    k_rank<<<nb, 256>>>(n);
    {
        long long warps = (n + 3) / 4;
        int blocks = (int)((warps * 32 + 255) / 256);
        k_gather<<<blocks, 256>>>(coords, feats, outc, outf, n);
    }
    k_multi<<<nb, 256>>>(coords, feats, outc, outf, n);
    k_final<<<256, 256>>>(outc, outf);
}